// round 2
// baseline (speedup 1.0000x reference)
#include <cuda_runtime.h>

#define NB    512     // batches
#define NKV   512     // kv sequence length
#define DIM   256     // feature dim
#define NH    8       // heads
#define DH    64      // dim per head
#define INNER 512     // NH*DH
#define TOPK  4

#define OUT_ELEMS   (NB * DIM)          // 131072
#define IDX_BASE    OUT_ELEMS
#define IDX_ELEMS   (NB * TOPK)         // 2048

// ---------------- device scratch (no allocations allowed) ----------------
__device__ float g_Q  [NB * INNER];       // [b][i]       q projection
__device__ float g_T  [NB * DIM * NH];    // [b][c][h]    folded key weights
__device__ float g_CTX[NB * NH * DIM];    // [b][h][d]    normalized context
__device__ float g_HIN[NB * INNER];       // [b][i]       ctx @ Wv (blockdiag)

// ================= K1: g_Q = inp_q (512x256) @ Wq (256x512) =================
__global__ __launch_bounds__(256) void k_qproj(const float* __restrict__ A,
                                               const float* __restrict__ Bm) {
    __shared__ float As[32 * 68];
    __shared__ float Bs[32 * 68];
    const int tid = threadIdx.x;
    const int tr = tid >> 4, tc = tid & 15;
    const int m0 = blockIdx.y * 64, n0 = blockIdx.x * 64;
    float acc[4][4] = {};
    for (int k0 = 0; k0 < DIM; k0 += 32) {
        #pragma unroll
        for (int s = 0; s < 8; s++) {
            int id = tid + 256 * s;
            int k = id & 31, m = id >> 5;
            As[k * 68 + m] = A[(m0 + m) * DIM + k0 + k];
        }
        #pragma unroll
        for (int s = 0; s < 8; s++) {
            int id = tid + 256 * s;
            int n = id & 63, k = id >> 6;
            Bs[k * 68 + n] = Bm[(k0 + k) * INNER + n0 + n];
        }
        __syncthreads();
        #pragma unroll
        for (int k = 0; k < 32; k++) {
            float4 a = *(const float4*)&As[k * 68 + tr * 4];
            float4 b = *(const float4*)&Bs[k * 68 + tc * 4];
            float av[4] = {a.x, a.y, a.z, a.w};
            float bv[4] = {b.x, b.y, b.z, b.w};
            #pragma unroll
            for (int i = 0; i < 4; i++)
                #pragma unroll
                for (int j = 0; j < 4; j++) acc[i][j] += av[i] * bv[j];
        }
        __syncthreads();
    }
    #pragma unroll
    for (int i = 0; i < 4; i++)
        #pragma unroll
        for (int j = 0; j < 4; j++)
            g_Q[(m0 + tr * 4 + i) * INNER + n0 + tc * 4 + j] = acc[i][j];
}

// ===== K2: g_T[b][c][h] = sum_e Wk[c][h*64+e] * g_Q[b][h*64+e]  (per head) =====
__global__ __launch_bounds__(256) void k_buildT(const float* __restrict__ Wk) {
    __shared__ float As[32 * 68];
    __shared__ float Bs[32 * 68];
    const int tid = threadIdx.x;
    const int tr = tid >> 4, tc = tid & 15;
    const int n0 = blockIdx.x * 64;        // c tile (0..255)
    const int m0 = blockIdx.y * 64;        // b tile
    const int h  = blockIdx.z;
    float acc[4][4] = {};
    for (int k0 = 0; k0 < DH; k0 += 32) {
        #pragma unroll
        for (int s = 0; s < 8; s++) {
            int id = tid + 256 * s;
            int k = id & 31, m = id >> 5;
            As[k * 68 + m] = g_Q[(m0 + m) * INNER + h * DH + k0 + k];
        }
        #pragma unroll
        for (int s = 0; s < 8; s++) {
            int id = tid + 256 * s;
            int k = id & 31, n = id >> 5;
            Bs[k * 68 + n] = Wk[(n0 + n) * INNER + h * DH + k0 + k];
        }
        __syncthreads();
        #pragma unroll
        for (int k = 0; k < 32; k++) {
            float4 a = *(const float4*)&As[k * 68 + tr * 4];
            float4 b = *(const float4*)&Bs[k * 68 + tc * 4];
            float av[4] = {a.x, a.y, a.z, a.w};
            float bv[4] = {b.x, b.y, b.z, b.w};
            #pragma unroll
            for (int i = 0; i < 4; i++)
                #pragma unroll
                for (int j = 0; j < 4; j++) acc[i][j] += av[i] * bv[j];
        }
        __syncthreads();
    }
    #pragma unroll
    for (int i = 0; i < 4; i++)
        #pragma unroll
        for (int j = 0; j < 4; j++)
            g_T[(m0 + tr * 4 + i) * (DIM * NH) + (n0 + tc * 4 + j) * NH + h] = acc[i][j];
}

// ================= K3: main attention kernel (one CTA per batch) =================
// smem plan (floats):
//   s_kv : 256*68 = 17408   (pass1: [256 j][68 pad];  ctx: [64 j][256 d])
//   s_t  : 2048             ([c][h])
//   s_e  : 4096             (exp(dots) [j][h])
//   s_hs : 512              (head_sum)
//   s_rdn: 8                (1/denom per head)
//   s_wv : 8,  s_wi : 8     (topk reduction scratch)
#define SM_KV   0
#define SM_T    17408
#define SM_E    (SM_T + 2048)
#define SM_HS   (SM_E + 4096)
#define SM_RDN  (SM_HS + 512)
#define SM_WV   (SM_RDN + 8)
#define SM_WI   (SM_WV + 8)
#define SM_FLOATS (SM_WI + 8)
#define SMEM_BYTES (SM_FLOATS * 4)

__global__ __launch_bounds__(256, 2) void k_attn_main(
        const float* __restrict__ kv_all, const int* __restrict__ mask_all,
        float* __restrict__ outp, int out_size) {
    extern __shared__ float sm[];
    float* s_kv  = sm + SM_KV;
    float* s_t   = sm + SM_T;
    float* s_e   = sm + SM_E;
    float* s_hs  = sm + SM_HS;
    float* s_rdn = sm + SM_RDN;
    float* s_wv  = sm + SM_WV;
    int*   s_wi  = (int*)(sm + SM_WI);

    const int b   = blockIdx.x;
    const int tid = threadIdx.x;
    const int wrp = tid >> 5, lane = tid & 31;

    const float4* kv4   = (const float4*)(kv_all + (size_t)b * NKV * DIM);
    const int*    maskb = mask_all + b * NKV;

    // load folded key weights T[b] -> s_t  (2048 floats = 512 float4)
    {
        const float4* T4 = (const float4*)(g_T + (size_t)b * DIM * NH);
        float4* st4 = (float4*)s_t;
        st4[tid]       = T4[tid];
        st4[tid + 256] = T4[tid + 256];
    }

    float c[NH] = {};   // context accumulator: this thread owns feature dim d = tid

    for (int jt = 0; jt < 2; jt++) {
        // ---- pass 1: dots for rows [jt*256, jt*256+256), this thread owns j row = jt*256+tid
        float acc[NH] = {};
        for (int dc = 0; dc < 4; dc++) {
            __syncthreads();   // also covers s_t stores on first iteration
            #pragma unroll
            for (int k = 0; k < 16; k++) {
                int id = tid + 256 * k;
                int j = id >> 4, c4 = id & 15;
                *(float4*)&s_kv[j * 68 + c4 * 4] = kv4[(jt * 256 + j) * 64 + dc * 16 + c4];
            }
            __syncthreads();
            const float4* kr4 = (const float4*)&s_kv[tid * 68];
            const float4* t2  = (const float4*)(s_t + dc * 512);
            #pragma unroll
            for (int d4 = 0; d4 < 16; d4++) {
                float4 kq = kr4[d4];
                float kvv[4] = {kq.x, kq.y, kq.z, kq.w};
                #pragma unroll
                for (int i = 0; i < 4; i++) {
                    float4 ta = t2[d4 * 8 + 2 * i];
                    float4 tb = t2[d4 * 8 + 2 * i + 1];
                    acc[0] += kvv[i] * ta.x; acc[1] += kvv[i] * ta.y;
                    acc[2] += kvv[i] * ta.z; acc[3] += kvv[i] * ta.w;
                    acc[4] += kvv[i] * tb.x; acc[5] += kvv[i] * tb.y;
                    acc[6] += kvv[i] * tb.z; acc[7] += kvv[i] * tb.w;
                }
            }
        }
        // mask + scale + exp (no max subtraction needed: dots ~ N(0,1), masked -> exp(-1e4)=0)
        {
            int j = jt * 256 + tid;
            float neg = (maskb[j] != 0) ? 0.0f : -10000.0f;
            float e0 = __expf(acc[0] * 0.125f + neg);
            float e1 = __expf(acc[1] * 0.125f + neg);
            float e2 = __expf(acc[2] * 0.125f + neg);
            float e3 = __expf(acc[3] * 0.125f + neg);
            float e4v = __expf(acc[4] * 0.125f + neg);
            float e5 = __expf(acc[5] * 0.125f + neg);
            float e6 = __expf(acc[6] * 0.125f + neg);
            float e7 = __expf(acc[7] * 0.125f + neg);
            ((float4*)s_e)[j * 2]     = make_float4(e0, e1, e2, e3);
            ((float4*)s_e)[j * 2 + 1] = make_float4(e4v, e5, e6, e7);
        }
        // ---- ctx accumulation over the same 256 rows (kv re-read is L2-hot)
        for (int st = 0; st < 4; st++) {
            __syncthreads();   // covers s_e stores (st==0) and previous s_kv use
            #pragma unroll
            for (int k = 0; k < 16; k++) {
                int id = tid + 256 * k;
                int j = id >> 6, c4 = id & 63;
                ((float4*)s_kv)[j * 64 + c4] = kv4[(jt * 256 + st * 64 + j) * 64 + c4];
            }
            __syncthreads();
            const float4* e4 = (const float4*)(s_e + (jt * 256 + st * 64) * 8);
            #pragma unroll 4
            for (int j = 0; j < 64; j++) {
                float kvv = s_kv[j * 256 + tid];
                float4 w0 = e4[2 * j];
                float4 w1 = e4[2 * j + 1];
                c[0] += w0.x * kvv; c[1] += w0.y * kvv; c[2] += w0.z * kvv; c[3] += w0.w * kvv;
                c[4] += w1.x * kvv; c[5] += w1.y * kvv; c[6] += w1.z * kvv; c[7] += w1.w * kvv;
            }
        }
    }
    __syncthreads();

    // ---- per-head denominators: warp w sums exp over all j for head h=w
    {
        float sum = 0.0f;
        #pragma unroll
        for (int m = 0; m < 16; m++) sum += s_e[(lane + 32 * m) * 8 + wrp];
        #pragma unroll
        for (int off = 16; off >= 1; off >>= 1) sum += __shfl_xor_sync(0xFFFFFFFFu, sum, off);
        if (lane == 0) s_rdn[wrp] = 1.0f / sum;
    }
    __syncthreads();

    float rdn[NH];
    #pragma unroll
    for (int h = 0; h < NH; h++) rdn[h] = s_rdn[h];

    // ---- head_sum[j] = sum_h attn[h][j]
    #pragma unroll
    for (int r = 0; r < 2; r++) {
        int j = tid + 256 * r;
        float4 w0 = ((const float4*)s_e)[j * 2];
        float4 w1 = ((const float4*)s_e)[j * 2 + 1];
        float hs = w0.x * rdn[0] + w0.y * rdn[1] + w0.z * rdn[2] + w0.w * rdn[3]
                 + w1.x * rdn[4] + w1.y * rdn[5] + w1.z * rdn[6] + w1.w * rdn[7];
        s_hs[j] = hs;
    }
    __syncthreads();

    // ---- top-4 by iterative argmax (tie -> lowest index, matching lax.top_k)
    const bool write_idx = (out_size >= IDX_BASE + IDX_ELEMS);
    for (int it = 0; it < TOPK; it++) {
        float v = s_hs[tid]; int idx = tid;
        float v1 = s_hs[tid + 256];
        if (v1 > v) { v = v1; idx = tid + 256; }
        #pragma unroll
        for (int off = 16; off >= 1; off >>= 1) {
            float ov = __shfl_xor_sync(0xFFFFFFFFu, v, off);
            int   oi = __shfl_xor_sync(0xFFFFFFFFu, idx, off);
            if (ov > v || (ov == v && oi < idx)) { v = ov; idx = oi; }
        }
        if (lane == 0) { s_wv[wrp] = v; s_wi[wrp] = idx; }
        __syncthreads();
        if (tid == 0) {
            float bv = s_wv[0]; int bi = s_wi[0];
            #pragma unroll
            for (int k = 1; k < 8; k++)
                if (s_wv[k] > bv || (s_wv[k] == bv && s_wi[k] < bi)) { bv = s_wv[k]; bi = s_wi[k]; }
            if (write_idx) outp[IDX_BASE + b * TOPK + it] = (float)bi;
            s_hs[bi] = -1e30f;
        }
        __syncthreads();
    }

    // ---- store normalized context
    #pragma unroll
    for (int h = 0; h < NH; h++)
        g_CTX[(size_t)b * NH * DIM + h * DIM + tid] = c[h] * rdn[h];
}

// ===== K4: g_HIN[b][h*64+e] = sum_d g_CTX[b][h][d] * Wv[d][h*64+e] =====
__global__ __launch_bounds__(256) void k_hin(const float* __restrict__ Wv) {
    __shared__ float As[32 * 68];
    __shared__ float Bs[32 * 68];
    const int tid = threadIdx.x;
    const int tr = tid >> 4, tc = tid & 15;
    const int m0 = blockIdx.x * 64;   // b tile
    const int h  = blockIdx.y;
    float acc[4][4] = {};
    for (int k0 = 0; k0 < DIM; k0 += 32) {
        #pragma unroll
        for (int s = 0; s < 8; s++) {
            int id = tid + 256 * s;
            int k = id & 31, m = id >> 5;
            As[k * 68 + m] = g_CTX[(m0 + m) * (NH * DIM) + h * DIM + k0 + k];
        }
        #pragma unroll
        for (int s = 0; s < 8; s++) {
            int id = tid + 256 * s;
            int n = id & 63, k = id >> 6;
            Bs[k * 68 + n] = Wv[(k0 + k) * INNER + h * DH + n];
        }
        __syncthreads();
        #pragma unroll
        for (int k = 0; k < 32; k++) {
            float4 a = *(const float4*)&As[k * 68 + tr * 4];
            float4 b = *(const float4*)&Bs[k * 68 + tc * 4];
            float av[4] = {a.x, a.y, a.z, a.w};
            float bv[4] = {b.x, b.y, b.z, b.w};
            #pragma unroll
            for (int i = 0; i < 4; i++)
                #pragma unroll
                for (int j = 0; j < 4; j++) acc[i][j] += av[i] * bv[j];
        }
        __syncthreads();
    }
    #pragma unroll
    for (int i = 0; i < 4; i++)
        #pragma unroll
        for (int j = 0; j < 4; j++)
            g_HIN[(m0 + tr * 4 + i) * INNER + h * DH + tc * 4 + j] = acc[i][j];
}

// ===== K5: out = g_HIN (512x512) @ Wo (512x256) + bo =====
__global__ __launch_bounds__(256) void k_outproj(const float* __restrict__ Wo,
                                                 const float* __restrict__ bo,
                                                 float* __restrict__ outp) {
    __shared__ float As[32 * 68];
    __shared__ float Bs[32 * 68];
    const int tid = threadIdx.x;
    const int tr = tid >> 4, tc = tid & 15;
    const int n0 = blockIdx.x * 64;   // output dim tile (256)
    const int m0 = blockIdx.y * 64;   // b tile
    float acc[4][4] = {};
    for (int k0 = 0; k0 < INNER; k0 += 32) {
        #pragma unroll
        for (int s = 0; s < 8; s++) {
            int id = tid + 256 * s;
            int k = id & 31, m = id >> 5;
            As[k * 68 + m] = g_HIN[(m0 + m) * INNER + k0 + k];
        }
        #pragma unroll
        for (int s = 0; s < 8; s++) {
            int id = tid + 256 * s;
            int n = id & 63, k = id >> 6;
            Bs[k * 68 + n] = Wo[(k0 + k) * DIM + n0 + n];
        }
        __syncthreads();
        #pragma unroll
        for (int k = 0; k < 32; k++) {
            float4 a = *(const float4*)&As[k * 68 + tr * 4];
            float4 b = *(const float4*)&Bs[k * 68 + tc * 4];
            float av[4] = {a.x, a.y, a.z, a.w};
            float bv[4] = {b.x, b.y, b.z, b.w};
            #pragma unroll
            for (int i = 0; i < 4; i++)
                #pragma unroll
                for (int j = 0; j < 4; j++) acc[i][j] += av[i] * bv[j];
        }
        __syncthreads();
    }
    #pragma unroll
    for (int i = 0; i < 4; i++)
        #pragma unroll
        for (int j = 0; j < 4; j++)
            outp[(m0 + tr * 4 + i) * DIM + n0 + tc * 4 + j] = acc[i][j] + bo[n0 + tc * 4 + j];
}

// =============================== launch ===============================
extern "C" void kernel_launch(void* const* d_in, const int* in_sizes, int n_in,
                              void* d_out, int out_size) {
    const float* inp_q  = (const float*)d_in[0];
    const float* inp_kv = (const float*)d_in[1];
    const int*   amask  = (const int*)  d_in[2];
    const float* Wq     = (const float*)d_in[3];
    const float* Wk     = (const float*)d_in[4];
    const float* Wv     = (const float*)d_in[5];
    const float* Wo     = (const float*)d_in[6];
    const float* bo     = (const float*)d_in[7];
    float* outp = (float*)d_out;

    (void)cudaFuncSetAttribute(k_attn_main, cudaFuncAttributeMaxDynamicSharedMemorySize, SMEM_BYTES);

    k_qproj  <<<dim3(8, 8),    256>>>(inp_q, Wq);
    k_buildT <<<dim3(4, 8, 8), 256>>>(Wk);
    k_attn_main<<<NB, 256, SMEM_BYTES>>>(inp_kv, amask, outp, out_size);
    k_hin    <<<dim3(8, 8),    256>>>(Wv);
    k_outproj<<<dim3(4, 8),    256>>>(Wo, bo, outp);
}

// round 4
// speedup vs baseline: 1.2647x; 1.2647x over previous
#include <cuda_runtime.h>

#define NB    512
#define NKV   512
#define DIM   256
#define NH    8
#define DH    64
#define INNER 512
#define TOPK  4

#define OUT_ELEMS   (NB * DIM)          // 131072
#define IDX_BASE    OUT_ELEMS
#define IDX_ELEMS   (NB * TOPK)

typedef unsigned long long ull;

// ---------------- device scratch ----------------
__device__ float g_M   [DIM * 2048];        // [d][c*8+h]   folded Wq*Wk
__device__ float g_T   [NB * 2048];         // [b][c*8+h]
__device__ float g_W2  [2048 * DIM];        // [(h*256+d)][o]  folded Wv*Wo
__device__ float g_CTXF[NB * 2048];         // [b][h*256+d] normalized context
__device__ float g_P   [8 * NB * DIM];      // split-K partials for out

// ---------------- f32x2 helpers ----------------
__device__ __forceinline__ void ffma2(ull& d, ull a, ull b) {
    asm("fma.rn.f32x2 %0, %1, %2, %0;" : "+l"(d) : "l"(a), "l"(b));
}
__device__ __forceinline__ ull dup2(float x) {
    ull r; asm("mov.b64 %0, {%1, %1};" : "=l"(r) : "f"(x)); return r;
}
__device__ __forceinline__ void unpack2(ull v, float& lo, float& hi) {
    asm("mov.b64 {%0, %1}, %2;" : "=f"(lo), "=f"(hi) : "l"(v));
}

// ========== K1: fold weights ==========
// z<8 : M[d][c*8+h]      = sum_e Wq[d][h*64+e] * Wk[c][h*64+e]   (h = z)
// z>=8: W2[(h*256+d)][o] = sum_e Wv[d][h*64+e] * Wo[h*64+e][o]   (h = z-8)
__global__ __launch_bounds__(256) void k_fold(const float* __restrict__ Wq,
                                              const float* __restrict__ Wk,
                                              const float* __restrict__ Wv,
                                              const float* __restrict__ Wo) {
    __shared__ float As[64 * 68];
    __shared__ float Bs[64 * 68];
    const int tid = threadIdx.x;
    const int tr = tid >> 4, tc = tid & 15;
    const int x0 = blockIdx.x * 64, y0 = blockIdx.y * 64;
    const int z = blockIdx.z;
    const int h = z & 7;
    const bool w2 = (z >= 8);

    if (!w2) {
        #pragma unroll
        for (int s = 0; s < 16; s++) {
            int id = tid + 256 * s;
            int e = id & 63, r = id >> 6;
            As[e * 68 + r] = Wq[(x0 + r) * INNER + h * DH + e];
            Bs[e * 68 + r] = Wk[(y0 + r) * INNER + h * DH + e];
        }
    } else {
        #pragma unroll
        for (int s = 0; s < 16; s++) {
            int id = tid + 256 * s;
            int e = id & 63, r = id >> 6;
            As[e * 68 + r] = Wv[(x0 + r) * INNER + h * DH + e];
        }
        #pragma unroll
        for (int s = 0; s < 16; s++) {
            int id = tid + 256 * s;
            int r = id & 63, e = id >> 6;
            Bs[e * 68 + r] = Wo[(h * DH + e) * DIM + y0 + r];
        }
    }
    __syncthreads();

    float acc[4][4] = {};
    #pragma unroll 8
    for (int e = 0; e < 64; e++) {
        float4 a = *(const float4*)&As[e * 68 + tr * 4];
        float4 b = *(const float4*)&Bs[e * 68 + tc * 4];
        float av[4] = {a.x, a.y, a.z, a.w};
        float bv[4] = {b.x, b.y, b.z, b.w};
        #pragma unroll
        for (int i = 0; i < 4; i++)
            #pragma unroll
            for (int j = 0; j < 4; j++) acc[i][j] += av[i] * bv[j];
    }

    if (!w2) {
        #pragma unroll
        for (int i = 0; i < 4; i++)
            #pragma unroll
            for (int j = 0; j < 4; j++)
                g_M[(x0 + tr * 4 + i) * 2048 + (y0 + tc * 4 + j) * 8 + h] = acc[i][j];
    } else {
        #pragma unroll
        for (int i = 0; i < 4; i++)
            #pragma unroll
            for (int j = 0; j < 4; j++)
                g_W2[(h * 256 + x0 + tr * 4 + i) * 256 + y0 + tc * 4 + j] = acc[i][j];
    }
}

// ========== K2 / K5a: unified f32x2 GEMM, tile 128m x 64n, reg-prefetch ==========
// mode 0: C=g_T    = Aext(inp_q)[512x256] @ g_M[256x2048]
// mode 1: C=g_P[z] = g_CTXF[512x2048 slice k] @ g_W2[2048x256]   (split-K via blockIdx.z)
__global__ __launch_bounds__(256) void k_gemm(const float* __restrict__ Aext, int mode) {
    __shared__ float As[32 * 132];   // [k][m], pad 132
    __shared__ float Bs[32 * 68];    // [k][n], pad 68
    const int tid = threadIdx.x;
    const float* A; const float* B; float* C;
    int lda, ldb, ldc;
    if (mode == 0) { A = Aext;   lda = 256;  B = g_M;  ldb = 2048; C = g_T; ldc = 2048; }
    else           { A = g_CTXF; lda = 2048; B = g_W2; ldb = 256;  C = g_P + (size_t)blockIdx.z * (NB * DIM); ldc = 256; }
    const int kbase = blockIdx.z * 256;   // mode0: z=0 only
    const int m0 = blockIdx.y * 128, n0 = blockIdx.x * 64;
    const int tr = tid >> 4, tc = tid & 15;

    ull acc[4][4];
    #pragma unroll
    for (int i = 0; i < 4; i++)
        #pragma unroll
        for (int j = 0; j < 4; j++) acc[i][j] = 0ull;

    float4 pa[4], pb[2];
    // prefetch chunk 0
    #pragma unroll
    for (int s = 0; s < 4; s++) {
        int id = tid + 256 * s; int m = id >> 3, kq = id & 7;
        pa[s] = *(const float4*)&A[(size_t)(m0 + m) * lda + kbase + kq * 4];
    }
    #pragma unroll
    for (int s = 0; s < 2; s++) {
        int id = tid + 256 * s; int k = id >> 4, nq = id & 15;
        pb[s] = *(const float4*)&B[(size_t)(kbase + k) * ldb + n0 + nq * 4];
    }

    for (int k0 = 0; k0 < 256; k0 += 32) {
        #pragma unroll
        for (int s = 0; s < 4; s++) {
            int id = tid + 256 * s; int m = id >> 3, kq = id & 7;
            As[(kq * 4 + 0) * 132 + m] = pa[s].x;
            As[(kq * 4 + 1) * 132 + m] = pa[s].y;
            As[(kq * 4 + 2) * 132 + m] = pa[s].z;
            As[(kq * 4 + 3) * 132 + m] = pa[s].w;
        }
        #pragma unroll
        for (int s = 0; s < 2; s++) {
            int id = tid + 256 * s; int k = id >> 4, nq = id & 15;
            *(float4*)&Bs[k * 68 + nq * 4] = pb[s];
        }
        __syncthreads();
        if (k0 + 32 < 256) {
            #pragma unroll
            for (int s = 0; s < 4; s++) {
                int id = tid + 256 * s; int m = id >> 3, kq = id & 7;
                pa[s] = *(const float4*)&A[(size_t)(m0 + m) * lda + kbase + k0 + 32 + kq * 4];
            }
            #pragma unroll
            for (int s = 0; s < 2; s++) {
                int id = tid + 256 * s; int k = id >> 4, nq = id & 15;
                pb[s] = *(const float4*)&B[(size_t)(kbase + k0 + 32 + k) * ldb + n0 + nq * 4];
            }
        }
        #pragma unroll 4
        for (int k = 0; k < 32; k++) {
            ulonglong2 a01 = *(const ulonglong2*)&As[k * 132 + tr * 8];
            ulonglong2 a23 = *(const ulonglong2*)&As[k * 132 + tr * 8 + 4];
            float4 b4 = *(const float4*)&Bs[k * 68 + tc * 4];
            ull db0 = dup2(b4.x), db1 = dup2(b4.y), db2 = dup2(b4.z), db3 = dup2(b4.w);
            ffma2(acc[0][0], a01.x, db0); ffma2(acc[0][1], a01.x, db1);
            ffma2(acc[0][2], a01.x, db2); ffma2(acc[0][3], a01.x, db3);
            ffma2(acc[1][0], a01.y, db0); ffma2(acc[1][1], a01.y, db1);
            ffma2(acc[1][2], a01.y, db2); ffma2(acc[1][3], a01.y, db3);
            ffma2(acc[2][0], a23.x, db0); ffma2(acc[2][1], a23.x, db1);
            ffma2(acc[2][2], a23.x, db2); ffma2(acc[2][3], a23.x, db3);
            ffma2(acc[3][0], a23.y, db0); ffma2(acc[3][1], a23.y, db1);
            ffma2(acc[3][2], a23.y, db2); ffma2(acc[3][3], a23.y, db3);
        }
        __syncthreads();
    }

    #pragma unroll
    for (int mp = 0; mp < 4; mp++) {
        #pragma unroll
        for (int nn = 0; nn < 4; nn++) {
            float lo, hi; unpack2(acc[mp][nn], lo, hi);
            int m = m0 + tr * 8 + 2 * mp;
            C[(size_t)m * ldc + n0 + tc * 4 + nn]       = lo;
            C[(size_t)(m + 1) * ldc + n0 + tc * 4 + nn] = hi;
        }
    }
}

// ========== K3: attention — single DRAM read of kv, f32x2 hot loops ==========
#define AT_SMKV  0          // 64 x 260 = 16640
#define AT_SMT   16640      // 2048  [c][h]
#define AT_SME   18688      // 4096  exp(dots) [j 0..511][h]
#define AT_SMP   22784      // 4096  pass1 partials [j 0..63][cg 0..7][h]
#define AT_SMNEG 26880      // 512   mask offsets
#define AT_SMHS  27392      // 512   head_sum
#define AT_SMRDN 27904      // 8
#define AT_SMWV  27912      // 8
#define AT_SMWI  27920      // 8
#define AT_FLOATS 27928
#define AT_BYTES (AT_FLOATS * 4)

__global__ __launch_bounds__(256, 2) void k_attn(
        const float* __restrict__ kv_all, const int* __restrict__ mask_all,
        float* __restrict__ outp, int out_size) {
    extern __shared__ float sm[];
    float* s_kv  = sm + AT_SMKV;
    float* s_t   = sm + AT_SMT;
    float* s_e   = sm + AT_SME;
    float* s_pf  = sm + AT_SMP;
    float* s_neg = sm + AT_SMNEG;
    float* s_hs  = sm + AT_SMHS;
    float* s_rdn = sm + AT_SMRDN;
    float* s_wv  = sm + AT_SMWV;
    int*   s_wi  = (int*)(sm + AT_SMWI);

    const int b   = blockIdx.x;
    const int tid = threadIdx.x;
    const int wrp = tid >> 5, lane = tid & 31;
    const int rp  = tid & 31, cg = tid >> 5;     // pass1: rows {rp, rp+32}, c-range [cg*32, cg*32+32)
    const int qd  = tid & 63, rq = tid >> 6;     // ctx: cols 4qd..4qd+3, rows [rq*16, rq*16+16)

    const float4* kvg = (const float4*)(kv_all + (size_t)b * NKV * DIM);

    // T[b] -> s_t ; mask -> s_neg
    {
        const float4* T4 = (const float4*)(g_T + (size_t)b * 2048);
        ((float4*)s_t)[tid]       = T4[tid];
        ((float4*)s_t)[tid + 256] = T4[tid + 256];
        const int* mb = mask_all + b * NKV;
        s_neg[tid]       = mb[tid]       ? 0.0f : -10000.0f;
        s_neg[tid + 256] = mb[tid + 256] ? 0.0f : -10000.0f;
    }

    ull ctxa[4][4];   // [hpair][col] — lanes hold (h even, h odd)
    #pragma unroll
    for (int i = 0; i < 4; i++)
        #pragma unroll
        for (int j = 0; j < 4; j++) ctxa[i][j] = 0ull;

    for (int tile = 0; tile < 8; tile++) {
        __syncthreads();   // protects s_kv reuse (prev ctx) + s_t/s_neg (tile 0)
        // load kv tile 64x256 -> s_kv[j][c] pad 260   (64 float4 per row!)
        #pragma unroll
        for (int s = 0; s < 16; s++) {
            int id = tid + 256 * s;
            int j = id >> 6, c4 = id & 63;
            *(float4*)&s_kv[j * 260 + c4 * 4] = kvg[(tile * 64 + j) * 64 + c4];
        }
        __syncthreads();

        // ---- pass1: partial dots over this thread's 32-c range, 2 rows
        ull accA[4] = {0ull, 0ull, 0ull, 0ull};
        ull accB[4] = {0ull, 0ull, 0ull, 0ull};
        const int c0 = cg * 32;
        #pragma unroll
        for (int c4 = 0; c4 < 32; c4 += 4) {
            float4 ka = *(const float4*)&s_kv[rp * 260 + c0 + c4];
            float4 kb = *(const float4*)&s_kv[(rp + 32) * 260 + c0 + c4];
            float kaf[4] = {ka.x, ka.y, ka.z, ka.w};
            float kbf[4] = {kb.x, kb.y, kb.z, kb.w};
            #pragma unroll
            for (int cc = 0; cc < 4; cc++) {
                const float* tp = &s_t[(c0 + c4 + cc) * 8];
                ulonglong2 t01 = *(const ulonglong2*)tp;        // h0h1, h2h3
                ulonglong2 t23 = *(const ulonglong2*)(tp + 4);  // h4h5, h6h7
                ull da = dup2(kaf[cc]);
                ull db = dup2(kbf[cc]);
                ffma2(accA[0], da, t01.x); ffma2(accA[1], da, t01.y);
                ffma2(accA[2], da, t23.x); ffma2(accA[3], da, t23.y);
                ffma2(accB[0], db, t01.x); ffma2(accB[1], db, t01.y);
                ffma2(accB[2], db, t23.x); ffma2(accB[3], db, t23.y);
            }
        }
        {   // store partials: ull layout [(r*8+cg)*4 + hp]  == float [r][cg][h]
            ulonglong2* sp2 = (ulonglong2*)s_pf;
            int baseA = (rp * 8 + cg) * 2;
            sp2[baseA]     = make_ulonglong2(accA[0], accA[1]);
            sp2[baseA + 1] = make_ulonglong2(accA[2], accA[3]);
            int baseB = ((rp + 32) * 8 + cg) * 2;
            sp2[baseB]     = make_ulonglong2(accB[0], accB[1]);
            sp2[baseB + 1] = make_ulonglong2(accB[2], accB[3]);
        }
        __syncthreads();

        // ---- reduce 8 c-groups + exp -> s_e
        #pragma unroll
        for (int s2 = 0; s2 < 2; s2++) {
            int slot = tid + 256 * s2;
            int j = slot >> 3, h = slot & 7;
            float sum = 0.0f;
            #pragma unroll
            for (int g = 0; g < 8; g++) sum += s_pf[(j * 8 + g) * 8 + h];
            s_e[(tile * 64 + j) * 8 + h] = __expf(sum * 0.125f + s_neg[tile * 64 + j]);
        }
        __syncthreads();

        // ---- ctx accumulate (kv still in smem — no second global read)
        #pragma unroll
        for (int jj = 0; jj < 16; jj++) {
            int j = rq * 16 + jj;
            float4 kv = *(const float4*)&s_kv[j * 260 + qd * 4];
            const float* ep = &s_e[(tile * 64 + j) * 8];
            ulonglong2 e01 = *(const ulonglong2*)ep;        // (h0,h1),(h2,h3)
            ulonglong2 e23 = *(const ulonglong2*)(ep + 4);  // (h4,h5),(h6,h7)
            ull d0 = dup2(kv.x), d1 = dup2(kv.y), d2 = dup2(kv.z), d3 = dup2(kv.w);
            ffma2(ctxa[0][0], d0, e01.x); ffma2(ctxa[0][1], d1, e01.x);
            ffma2(ctxa[0][2], d2, e01.x); ffma2(ctxa[0][3], d3, e01.x);
            ffma2(ctxa[1][0], d0, e01.y); ffma2(ctxa[1][1], d1, e01.y);
            ffma2(ctxa[1][2], d2, e01.y); ffma2(ctxa[1][3], d3, e01.y);
            ffma2(ctxa[2][0], d0, e23.x); ffma2(ctxa[2][1], d1, e23.x);
            ffma2(ctxa[2][2], d2, e23.x); ffma2(ctxa[2][3], d3, e23.x);
            ffma2(ctxa[3][0], d0, e23.y); ffma2(ctxa[3][1], d1, e23.y);
            ffma2(ctxa[3][2], d2, e23.y); ffma2(ctxa[3][3], d3, e23.y);
        }
    }
    __syncthreads();

    // ---- per-head denominators (warp w = head w)
    {
        float sum = 0.0f;
        #pragma unroll
        for (int m = 0; m < 16; m++) sum += s_e[(lane + 32 * m) * 8 + wrp];
        #pragma unroll
        for (int off = 16; off >= 1; off >>= 1) sum += __shfl_xor_sync(0xFFFFFFFFu, sum, off);
        if (lane == 0) s_rdn[wrp] = 1.0f / sum;
    }
    __syncthreads();

    float rdn[NH];
    #pragma unroll
    for (int h = 0; h < NH; h++) rdn[h] = s_rdn[h];

    // ---- head_sum -> s_hs ; ctx partials -> s_red (aliases s_kv)
    #pragma unroll
    for (int r = 0; r < 2; r++) {
        int j = tid + 256 * r;
        float4 w0 = ((const float4*)s_e)[j * 2];
        float4 w1 = ((const float4*)s_e)[j * 2 + 1];
        s_hs[j] = w0.x * rdn[0] + w0.y * rdn[1] + w0.z * rdn[2] + w0.w * rdn[3]
                + w1.x * rdn[4] + w1.y * rdn[5] + w1.z * rdn[6] + w1.w * rdn[7];
    }
    {
        float* s_red = s_kv;   // 4 rq x 2048 = 8192 floats, fits in s_kv region
        #pragma unroll
        for (int hp = 0; hp < 4; hp++)
            #pragma unroll
            for (int col = 0; col < 4; col++) {
                float lo, hi; unpack2(ctxa[hp][col], lo, hi);
                int d = qd * 4 + col;
                s_red[rq * 2048 + (2 * hp) * 256 + d]     = lo;
                s_red[rq * 2048 + (2 * hp + 1) * 256 + d] = hi;
            }
    }
    __syncthreads();

    // ---- final ctx: sum 4 row-quarters, normalize, store flat [b][h*256+d]
    {
        const float* s_red = s_kv;
        #pragma unroll
        for (int k = 0; k < 8; k++) {
            int slot = tid + 256 * k;
            float v = s_red[slot] + s_red[2048 + slot] + s_red[4096 + slot] + s_red[6144 + slot];
            g_CTXF[(size_t)b * 2048 + slot] = v * rdn[slot >> 8];
        }
    }

    // ---- top-4 iterative argmax (lowest-index tie-break, matches lax.top_k)
    const bool write_idx = (out_size >= IDX_BASE + IDX_ELEMS);
    for (int it = 0; it < TOPK; it++) {
        float v = s_hs[tid]; int idx = tid;
        float v1 = s_hs[tid + 256];
        if (v1 > v) { v = v1; idx = tid + 256; }
        #pragma unroll
        for (int off = 16; off >= 1; off >>= 1) {
            float ov = __shfl_xor_sync(0xFFFFFFFFu, v, off);
            int   oi = __shfl_xor_sync(0xFFFFFFFFu, idx, off);
            if (ov > v || (ov == v && oi < idx)) { v = ov; idx = oi; }
        }
        if (lane == 0) { s_wv[wrp] = v; s_wi[wrp] = idx; }
        __syncthreads();
        if (tid == 0) {
            float bv = s_wv[0]; int bi = s_wi[0];
            #pragma unroll
            for (int k = 1; k < 8; k++)
                if (s_wv[k] > bv || (s_wv[k] == bv && s_wi[k] < bi)) { bv = s_wv[k]; bi = s_wi[k]; }
            if (write_idx) outp[IDX_BASE + b * TOPK + it] = (float)bi;
            s_hs[bi] = -1e30f;
        }
        __syncthreads();
    }
}

// ========== K5b: out = sum of 8 split-K partials + bo ==========
__global__ __launch_bounds__(256) void k_out(const float* __restrict__ bo,
                                             float* __restrict__ outp) {
    int i = blockIdx.x * 256 + threadIdx.x;   // float4 index, 32768 total
    const float4* P4 = (const float4*)g_P;
    float4 acc = ((const float4*)bo)[i & 63];
    #pragma unroll
    for (int z = 0; z < 8; z++) {
        float4 p = P4[z * 32768 + i];
        acc.x += p.x; acc.y += p.y; acc.z += p.z; acc.w += p.w;
    }
    ((float4*)outp)[i] = acc;
}

// =============================== launch ===============================
extern "C" void kernel_launch(void* const* d_in, const int* in_sizes, int n_in,
                              void* d_out, int out_size) {
    const float* inp_q  = (const float*)d_in[0];
    const float* inp_kv = (const float*)d_in[1];
    const int*   amask  = (const int*)  d_in[2];
    const float* Wq     = (const float*)d_in[3];
    const float* Wk     = (const float*)d_in[4];
    const float* Wv     = (const float*)d_in[5];
    const float* Wo     = (const float*)d_in[6];
    const float* bo     = (const float*)d_in[7];
    float* outp = (float*)d_out;

    (void)cudaFuncSetAttribute(k_attn, cudaFuncAttributeMaxDynamicSharedMemorySize, AT_BYTES);

    k_fold<<<dim3(4, 4, 16), 256>>>(Wq, Wk, Wv, Wo);
    k_gemm<<<dim3(32, 4, 1), 256>>>(inp_q, 0);     // T = inp_q @ M
    k_attn<<<NB, 256, AT_BYTES>>>(inp_kv, amask, outp, out_size);
    k_gemm<<<dim3(4, 4, 8), 256>>>(nullptr, 1);    // partials = ctx @ W2 (split-K 8)
    k_out <<<128, 256>>>(bo, outp);
}